// round 1
// baseline (speedup 1.0000x reference)
#include <cuda_runtime.h>
#include <math.h>

#define BB 32
#define SS 2048
#define HH 1024
#define SC 16          // s-chunks of 128 for column sums
#define NCHUNK 8       // GEMM N chunks (1024 / 128)
#define BM 128
#define BN 128
#define BK 16
#define PX 4           // smem pad

// -------- scratch (no allocations allowed) --------
__device__ float g_partial[BB * SC * HH];     // [B][SC][H] partial column sums
__device__ float g_mean[BB * HH];             // mean over S
__device__ float g_m0[BB * HH];               // mean * q
__device__ float g_v1[BB * HH];               // gate1 * Wh1
__device__ float g_v2[BB * HH];               // gate2 * Wh2
__device__ float g_pU[(size_t)BB * SS * NCHUNK]; // partial U per n-chunk
__device__ float g_alpha[BB * SS];            // softmax weights

// ---------------------------------------------------------------
// Pass 1: partial column sums of X over s-chunks (optionally alpha-weighted)
// grid (H/256, SC, B), block 256
// ---------------------------------------------------------------
__global__ void colsum_partial(const float* __restrict__ X, int weighted) {
    int h  = blockIdx.x * 256 + threadIdx.x;
    int sc = blockIdx.y;
    int b  = blockIdx.z;
    const float* base = X + ((size_t)b * SS + (size_t)sc * 128) * HH + h;
    float acc = 0.f;
    if (weighted) {
        const float* w = g_alpha + b * SS + sc * 128;
#pragma unroll 4
        for (int i = 0; i < 128; i++)
            acc = fmaf(__ldg(&w[i]), base[(size_t)i * HH], acc);
    } else {
#pragma unroll 4
        for (int i = 0; i < 128; i++)
            acc += base[(size_t)i * HH];
    }
    g_partial[(b * SC + sc) * HH + h] = acc;
}

// ---------------------------------------------------------------
// Reduce partials -> mean, m0 = mean*q, and write u_att0 to out[0]
// grid B*H/256
// ---------------------------------------------------------------
__global__ void finalize_mean(const float* __restrict__ q, float* __restrict__ out) {
    int idx = blockIdx.x * 256 + threadIdx.x;   // < B*H
    int b = idx >> 10;
    int h = idx & (HH - 1);
    float s = 0.f;
#pragma unroll
    for (int c = 0; c < SC; c++) s += g_partial[(b * SC + c) * HH + h];
    float mean = s * (1.f / (float)SS);
    g_mean[idx] = mean;
    g_m0[idx]   = mean * q[idx];
    out[idx]    = mean;                          // u_att0
}

// ---------------------------------------------------------------
// Reduce weighted partials -> u_att slot
// ---------------------------------------------------------------
__global__ void finalize_att(float* __restrict__ out, int slot) {
    int idx = blockIdx.x * 256 + threadIdx.x;
    int b = idx >> 10;
    int h = idx & (HH - 1);
    float s = 0.f;
#pragma unroll
    for (int c = 0; c < SC; c++) s += g_partial[(b * SC + c) * HH + h];
    out[(size_t)slot * BB * HH + idx] = s;
}

// ---------------------------------------------------------------
// v vectors for both hops: v[b,d] = tanh(scale * (m0 @ Wm)[b,d]) * Wh[d]
// m1 = 2*m0, so hop2 uses scale=2 with Wm2/Wh2.
// grid (H/256, B/8, 2), block 256. smem holds 8 rows of m0.
// ---------------------------------------------------------------
__global__ void prep_v(const float* __restrict__ Wm1, const float* __restrict__ Wh1,
                       const float* __restrict__ Wm2, const float* __restrict__ Wh2) {
    __shared__ float sm[8 * HH];
    int d   = blockIdx.x * 256 + threadIdx.x;
    int b0  = blockIdx.y * 8;
    int hop = blockIdx.z;
    const float* Wm = hop ? Wm2 : Wm1;
    const float* Wh = hop ? Wh2 : Wh1;
    float scale = hop ? 2.f : 1.f;

    for (int i = threadIdx.x; i < 8 * HH; i += 256)
        sm[i] = g_m0[b0 * HH + i];
    __syncthreads();

    float acc[8];
#pragma unroll
    for (int j = 0; j < 8; j++) acc[j] = 0.f;

#pragma unroll 4
    for (int h = 0; h < HH; h++) {
        float w = Wm[(size_t)h * HH + d];
#pragma unroll
        for (int j = 0; j < 8; j++)
            acc[j] = fmaf(sm[j * HH + h], w, acc[j]);
    }
    float wh = Wh[d];
    float* v = hop ? g_v2 : g_v1;
#pragma unroll
    for (int j = 0; j < 8; j++)
        v[(b0 + j) * HH + d] = tanhf(scale * acc[j]) * wh;
}

// ---------------------------------------------------------------
// Big fused GEMM: partial U[row, nchunk] = sum_{d in chunk} tanh((X@W)[row,d]) * v[b,d]
// 128x128x16 tile, 256 threads, 8x8 per thread.
// grid (B*S/128, NCHUNK)
// ---------------------------------------------------------------
__global__ void __launch_bounds__(256) gemmU(const float* __restrict__ X,
                                             const float* __restrict__ W,
                                             int hop) {
    __shared__ float Xs[BK * (BM + PX)];
    __shared__ float Ws[BK * BN];

    int tid  = threadIdx.x;
    int row0 = blockIdx.x * BM;
    int n0   = blockIdx.y * BN;
    int bidx = row0 >> 11;                 // row0 / 2048 (BM divides S)
    const float* v = (hop ? g_v2 : g_v1) + bidx * HH + n0;

    int tx = tid & 15;                     // n group (8 cols each)
    int ty = tid >> 4;                     // m group (8 rows each)

    float acc[8][8];
#pragma unroll
    for (int i = 0; i < 8; i++)
#pragma unroll
        for (int j = 0; j < 8; j++) acc[i][j] = 0.f;

    int lkx = tid & 15;                    // X-load k
    int lmx = tid >> 4;                    // X-load m base
    int lnw = tid & 127;                   // W-load n
    int lkw = tid >> 7;                    // W-load k base

    for (int k0 = 0; k0 < HH; k0 += BK) {
#pragma unroll
        for (int p = 0; p < 8; p++) {
            int m = lmx + p * 16;
            Xs[lkx * (BM + PX) + m] = X[(size_t)(row0 + m) * HH + k0 + lkx];
        }
#pragma unroll
        for (int p = 0; p < 8; p++) {
            int kk = lkw + p * 2;
            Ws[kk * BN + lnw] = W[(size_t)(k0 + kk) * HH + n0 + lnw];
        }
        __syncthreads();

#pragma unroll
        for (int k = 0; k < BK; k++) {
            float4 a0 = *(const float4*)&Xs[k * (BM + PX) + ty * 8];
            float4 a1 = *(const float4*)&Xs[k * (BM + PX) + ty * 8 + 4];
            float4 b0 = *(const float4*)&Ws[k * BN + tx * 8];
            float4 b1 = *(const float4*)&Ws[k * BN + tx * 8 + 4];
            float av[8] = {a0.x, a0.y, a0.z, a0.w, a1.x, a1.y, a1.z, a1.w};
            float bv[8] = {b0.x, b0.y, b0.z, b0.w, b1.x, b1.y, b1.z, b1.w};
#pragma unroll
            for (int i = 0; i < 8; i++)
#pragma unroll
                for (int j = 0; j < 8; j++)
                    acc[i][j] = fmaf(av[i], bv[j], acc[i][j]);
        }
        __syncthreads();
    }

    // epilogue: tanh, dot with v, reduce over the 16 tx lanes
    float vr[8];
#pragma unroll
    for (int j = 0; j < 8; j++) vr[j] = v[tx * 8 + j];

#pragma unroll
    for (int i = 0; i < 8; i++) {
        float s = 0.f;
#pragma unroll
        for (int j = 0; j < 8; j++)
            s = fmaf(tanhf(acc[i][j]), vr[j], s);
#pragma unroll
        for (int off = 8; off > 0; off >>= 1)
            s += __shfl_down_sync(0xffffffffu, s, off, 16);
        if (tx == 0)
            g_pU[(size_t)(row0 + ty * 8 + i) * NCHUNK + blockIdx.y] = s;
    }
}

// ---------------------------------------------------------------
// Reduce pU over n-chunks + softmax over S per batch -> g_alpha
// grid B, block 256 (each thread handles 8 s positions)
// ---------------------------------------------------------------
__global__ void softmax_u() {
    int b = blockIdx.x;
    int tid = threadIdx.x;
    __shared__ float red[256];

    float u[8];
#pragma unroll
    for (int i = 0; i < 8; i++) {
        int s = tid + i * 256;
        const float* p = g_pU + ((size_t)b * SS + s) * NCHUNK;
        float t = 0.f;
#pragma unroll
        for (int c = 0; c < NCHUNK; c++) t += p[c];
        u[i] = t;
    }
    float m = u[0];
#pragma unroll
    for (int i = 1; i < 8; i++) m = fmaxf(m, u[i]);
    red[tid] = m;
    __syncthreads();
    for (int o = 128; o > 0; o >>= 1) {
        if (tid < o) red[tid] = fmaxf(red[tid], red[tid + o]);
        __syncthreads();
    }
    float mx = red[0];
    __syncthreads();

    float e[8];
    float sum = 0.f;
#pragma unroll
    for (int i = 0; i < 8; i++) { e[i] = expf(u[i] - mx); sum += e[i]; }
    red[tid] = sum;
    __syncthreads();
    for (int o = 128; o > 0; o >>= 1) {
        if (tid < o) red[tid] += red[tid + o];
        __syncthreads();
    }
    float inv = 1.f / red[0];
#pragma unroll
    for (int i = 0; i < 8; i++)
        g_alpha[b * SS + tid + i * 256] = e[i] * inv;
}

// ---------------------------------------------------------------
extern "C" void kernel_launch(void* const* d_in, const int* in_sizes, int n_in,
                              void* d_out, int out_size) {
    (void)in_sizes; (void)n_in; (void)out_size;
    const float* X   = (const float*)d_in[0];
    const float* q   = (const float*)d_in[1];
    const float* W1  = (const float*)d_in[2];
    const float* Wm1 = (const float*)d_in[3];
    const float* Wh1 = (const float*)d_in[4];
    const float* W2  = (const float*)d_in[5];
    const float* Wm2 = (const float*)d_in[6];
    const float* Wh2 = (const float*)d_in[7];
    float* out = (float*)d_out;

    dim3 cs(HH / 256, SC, BB);

    // mean pass + u_att0
    colsum_partial<<<cs, 256>>>(X, 0);
    finalize_mean<<<BB * HH / 256, 256>>>(q, out);

    // both hops' v vectors (m1 = 2*m0 has no dependence on hop1 output)
    prep_v<<<dim3(HH / 256, BB / 8, 2), 256>>>(Wm1, Wh1, Wm2, Wh2);

    // hop 1
    gemmU<<<dim3(BB * SS / BM, NCHUNK), 256>>>(X, W1, 0);
    softmax_u<<<BB, 256>>>();
    colsum_partial<<<cs, 256>>>(X, 1);
    finalize_att<<<BB * HH / 256, 256>>>(out, 1);

    // hop 2
    gemmU<<<dim3(BB * SS / BM, NCHUNK), 256>>>(X, W2, 1);
    softmax_u<<<BB, 256>>>();
    colsum_partial<<<cs, 256>>>(X, 1);
    finalize_att<<<BB * HH / 256, 256>>>(out, 2);
}

// round 3
// speedup vs baseline: 6.6796x; 6.6796x over previous
#include <cuda_runtime.h>
#include <cuda_bf16.h>
#include <math.h>
#include <stdint.h>

#define BB 32
#define SS 2048
#define HH 1024
#define SC 16
#define ROWS (BB*SS)          // 65536
#define NCHUNK 8

// ---------------- device scratch (no allocs allowed) ----------------
__device__ __nv_bfloat16 g_Xb[(size_t)ROWS * HH];   // 128 MB bf16 X
__device__ __nv_bfloat16 g_Wt1[HH * HH];            // W1^T bf16 [d][k]
__device__ __nv_bfloat16 g_Wt2[HH * HH];            // W2^T bf16
__device__ float g_partial [BB * SC * HH];
__device__ float g_partial2[BB * SC * HH];
__device__ float g_m0[BB * HH];
__device__ float g_v1[BB * HH];
__device__ float g_v2[BB * HH];
__device__ float g_pU[(size_t)2 * ROWS * NCHUNK];   // per-hop partial U
__device__ float g_alpha[2 * BB * SS];

// ---------------- helpers ----------------
__device__ __forceinline__ uint32_t sm_u32(const void* p) {
    uint32_t a;
    asm("{ .reg .u64 t; cvta.to.shared.u64 t, %1; cvt.u32.u64 %0, t; }" : "=r"(a) : "l"(p));
    return a;
}
__device__ __forceinline__ float ftanh(float x) {
    float y; asm("tanh.approx.f32 %0, %1;" : "=f"(y) : "f"(x)); return y;
}

#define CP16(dst, src) \
    asm volatile("cp.async.cg.shared.global [%0], [%1], 16;\n" \
        :: "r"(dst), "l"(__cvta_generic_to_global(src)))
#define CP_COMMIT()    asm volatile("cp.async.commit_group;\n" ::: "memory")
#define CP_WAIT(n)     asm volatile("cp.async.wait_group %0;\n" :: "n"(n) : "memory")

__device__ __forceinline__ void ldsm4(uint32_t& r0, uint32_t& r1, uint32_t& r2, uint32_t& r3, uint32_t a) {
    asm volatile("ldmatrix.sync.aligned.m8n8.x4.shared.b16 {%0,%1,%2,%3}, [%4];"
        : "=r"(r0), "=r"(r1), "=r"(r2), "=r"(r3) : "r"(a));
}
__device__ __forceinline__ void mma16816(float* d, const uint32_t* a, const uint32_t* b) {
    asm volatile("mma.sync.aligned.m16n8k16.row.col.f32.bf16.bf16.f32 "
        "{%0,%1,%2,%3}, {%4,%5,%6,%7}, {%8,%9}, {%0,%1,%2,%3};"
        : "+f"(d[0]), "+f"(d[1]), "+f"(d[2]), "+f"(d[3])
        : "r"(a[0]), "r"(a[1]), "r"(a[2]), "r"(a[3]), "r"(b[0]), "r"(b[1]));
}

// ---------------- SMEM layout for GEMM (dynamic) ----------------
// A: 2 stages x 128 rows x 128B (= 64 bf16 k), SW128
// B: 2 stages x 128 rows x 128B
#define SMA 0
#define SMB 32768
#define SMV 65536           // 128 floats of v
#define SMU 66048           // Upart[4][128] floats
#define SM_TOTAL 68096

// ---------------------------------------------------------------
// convert W -> bf16 transposed: Wt[d][k] = bf16(W[k][d])
// ---------------------------------------------------------------
__global__ void convW(const float* __restrict__ W1, const float* __restrict__ W2) {
    __shared__ float t[32][33];
    const float* W = blockIdx.z ? W2 : W1;
    __nv_bfloat16* Wt = blockIdx.z ? g_Wt2 : g_Wt1;
    int d0 = blockIdx.x * 32, k0 = blockIdx.y * 32;
    int tx = threadIdx.x, ty = threadIdx.y;
    for (int j = ty; j < 32; j += 8)
        t[j][tx] = W[(size_t)(k0 + j) * HH + d0 + tx];
    __syncthreads();
    for (int j = ty; j < 32; j += 8)
        Wt[(size_t)(d0 + j) * HH + k0 + tx] = __float2bfloat16(t[tx][j]);
}

// ---------------------------------------------------------------
// convert X -> bf16 + partial column sums (mean), one X pass
// ---------------------------------------------------------------
__global__ void convX_mean(const float* __restrict__ X) {
    int h  = blockIdx.x * 256 + threadIdx.x;
    int sc = blockIdx.y, b = blockIdx.z;
    size_t base = ((size_t)b * SS + (size_t)sc * 128) * HH + h;
    float acc = 0.f;
#pragma unroll 4
    for (int i = 0; i < 128; i++) {
        float x = X[base + (size_t)i * HH];
        acc += x;
        g_Xb[base + (size_t)i * HH] = __float2bfloat16(x);
    }
    g_partial[(b * SC + sc) * HH + h] = acc;
}

__global__ void finalize_mean(const float* __restrict__ q, float* __restrict__ out) {
    int idx = blockIdx.x * 256 + threadIdx.x;
    int b = idx >> 10, h = idx & (HH - 1);
    float s = 0.f;
#pragma unroll
    for (int c = 0; c < SC; c++) s += g_partial[(b * SC + c) * HH + h];
    float mean = s * (1.f / (float)SS);
    g_m0[idx] = mean * q[idx];
    out[idx]  = mean;                          // u_att0
}

// ---------------------------------------------------------------
// v[b,d] = tanh(scale*(m0@Wm)[b,d]) * Wh[d];  hop2: m1=2*m0 -> scale=2
// ---------------------------------------------------------------
__global__ void prep_v(const float* __restrict__ Wm1, const float* __restrict__ Wh1,
                       const float* __restrict__ Wm2, const float* __restrict__ Wh2) {
    __shared__ float sm[8 * HH];
    int d   = blockIdx.x * 256 + threadIdx.x;
    int b0  = blockIdx.y * 8;
    int hop = blockIdx.z;
    const float* Wm = hop ? Wm2 : Wm1;
    const float* Wh = hop ? Wh2 : Wh1;
    float scale = hop ? 2.f : 1.f;
    for (int i = threadIdx.x; i < 8 * HH; i += 256) sm[i] = g_m0[b0 * HH + i];
    __syncthreads();
    float acc[8];
#pragma unroll
    for (int j = 0; j < 8; j++) acc[j] = 0.f;
#pragma unroll 4
    for (int h = 0; h < HH; h++) {
        float w = Wm[(size_t)h * HH + d];
#pragma unroll
        for (int j = 0; j < 8; j++) acc[j] = fmaf(sm[j * HH + h], w, acc[j]);
    }
    float wh = Wh[d];
    float* v = hop ? g_v2 : g_v1;
#pragma unroll
    for (int j = 0; j < 8; j++) v[(b0 + j) * HH + d] = tanhf(scale * acc[j]) * wh;
}

// ---------------------------------------------------------------
// HMMA GEMM + fused tanh/v-dot epilogue.
// grid (NCHUNK, ROWS/128, 2). 256 threads = 2 (M) x 4 (N) warps.
// Warp tile 64x32, mma m16n8k16 bf16.
// ---------------------------------------------------------------
__device__ __forceinline__ void stage_load(uint32_t sb, int st,
                                           const __nv_bfloat16* Xrow,
                                           const __nv_bfloat16* Wrow,
                                           int k0, int tid) {
    uint32_t ab = sb + SMA + st * 16384;
    uint32_t bb = sb + SMB + st * 16384;
#pragma unroll
    for (int i = 0; i < 4; i++) {
        int c = tid + i * 256;            // 1024 16B-chunks
        int r = c >> 3, seg = c & 7;
        uint32_t off = (uint32_t)(r * 128 + seg * 16);
        uint32_t sw  = off ^ ((off >> 3) & 0x70);
        CP16(ab + sw, (const char*)(Xrow + (size_t)r * HH + k0) + seg * 16);
        CP16(bb + sw, (const char*)(Wrow + (size_t)r * HH + k0) + seg * 16);
    }
}

__global__ void __launch_bounds__(256, 2) gemm_mma() {
    extern __shared__ char smem[];
    uint32_t sb = sm_u32(smem);
    int tid = threadIdx.x, lane = tid & 31, wid = tid >> 5;
    int warpM = wid & 1, warpN = wid >> 1;           // 2 x 4
    int nch = blockIdx.x, rowt = blockIdx.y, hop = blockIdx.z;
    int row0 = rowt * 128, n0 = nch * 128;
    int b = rowt >> 4;

    const __nv_bfloat16* Xrow = g_Xb + (size_t)row0 * HH;
    const __nv_bfloat16* Wrow = (hop ? g_Wt2 : g_Wt1) + (size_t)n0 * HH;
    const float* v = (hop ? g_v2 : g_v1) + b * HH + n0;

    float* vs = (float*)(smem + SMV);
    float* su = (float*)(smem + SMU);
    if (tid < 128) vs[tid] = v[tid];

    float acc[4][4][4];
#pragma unroll
    for (int i = 0; i < 4; i++)
#pragma unroll
        for (int j = 0; j < 4; j++)
#pragma unroll
            for (int t = 0; t < 4; t++) acc[i][j][t] = 0.f;

    // ldmatrix lane addressing (SW128: xor value depends only on row%8)
    int rA = warpM * 64 + (lane & 15);
    uint32_t rxA = (uint32_t)((rA & 7) << 4);
    uint32_t aoff = (uint32_t)(((lane >> 4) & 1) << 4);    // k-half selector (bytes)
    int rB = warpN * 32 + (lane & 7) + ((lane & 16) >> 1);
    uint32_t rxB = (uint32_t)((rB & 7) << 4);
    uint32_t boff = (uint32_t)(((lane >> 3) & 1) << 4);

    stage_load(sb, 0, Xrow, Wrow, 0, tid);  CP_COMMIT();
    stage_load(sb, 1, Xrow, Wrow, 64, tid); CP_COMMIT();

    for (int kk = 0; kk < 16; kk++) {
        int st = kk & 1;
        if (kk < 15) { CP_WAIT(1); } else { CP_WAIT(0); }
        __syncthreads();

        uint32_t abase = sb + SMA + st * 16384;
        uint32_t bbase = sb + SMB + st * 16384;
#pragma unroll
        for (int s = 0; s < 4; s++) {
            uint32_t A[4][4];
#pragma unroll
            for (int i = 0; i < 4; i++) {
                uint32_t addr = abase + (uint32_t)((rA + i * 16) * 128)
                              + (((uint32_t)(s * 32) + aoff) ^ rxA);
                ldsm4(A[i][0], A[i][1], A[i][2], A[i][3], addr);
            }
            uint32_t Bf[4][2];
#pragma unroll
            for (int jj = 0; jj < 2; jj++) {
                uint32_t addr = bbase + (uint32_t)((rB + jj * 16) * 128)
                              + (((uint32_t)(s * 32) + boff) ^ rxB);
                ldsm4(Bf[jj*2][0], Bf[jj*2][1], Bf[jj*2+1][0], Bf[jj*2+1][1], addr);
            }
#pragma unroll
            for (int i = 0; i < 4; i++)
#pragma unroll
                for (int j = 0; j < 4; j++)
                    mma16816(acc[i][j], A[i], Bf[j]);
        }
        __syncthreads();
        if (kk < 14) {
            stage_load(sb, st, Xrow, Wrow, (kk + 2) * 64, tid);
            CP_COMMIT();
        }
    }

    // epilogue: tanh * v, reduce over n
    float vv[4][2];
#pragma unroll
    for (int j = 0; j < 4; j++) {
        int nl = warpN * 32 + j * 8 + (lane & 3) * 2;
        vv[j][0] = vs[nl]; vv[j][1] = vs[nl + 1];
    }
#pragma unroll
    for (int i = 0; i < 4; i++) {
        float r0 = 0.f, r1 = 0.f;
#pragma unroll
        for (int j = 0; j < 4; j++) {
            r0 = fmaf(ftanh(acc[i][j][0]), vv[j][0], r0);
            r0 = fmaf(ftanh(acc[i][j][1]), vv[j][1], r0);
            r1 = fmaf(ftanh(acc[i][j][2]), vv[j][0], r1);
            r1 = fmaf(ftanh(acc[i][j][3]), vv[j][1], r1);
        }
        r0 += __shfl_xor_sync(0xffffffffu, r0, 1);
        r0 += __shfl_xor_sync(0xffffffffu, r0, 2);
        r1 += __shfl_xor_sync(0xffffffffu, r1, 1);
        r1 += __shfl_xor_sync(0xffffffffu, r1, 2);
        if ((lane & 3) == 0) {
            int r = warpM * 64 + i * 16 + (lane >> 2);
            su[warpN * 128 + r]     = r0;
            su[warpN * 128 + r + 8] = r1;
        }
    }
    __syncthreads();
    if (tid < 128) {
        float s = su[tid] + su[128 + tid] + su[256 + tid] + su[384 + tid];
        g_pU[((size_t)hop * ROWS + row0 + tid) * NCHUNK + nch] = s;
    }
}

// ---------------------------------------------------------------
// reduce partial U + softmax over S, both hops. grid (B, 2), block 256.
// ---------------------------------------------------------------
__global__ void softmax_u() {
    int b = blockIdx.x, hop = blockIdx.y;
    int tid = threadIdx.x;
    __shared__ float red[256];
    const float* P = g_pU + ((size_t)hop * ROWS + (size_t)b * SS) * NCHUNK;
    float* al = g_alpha + (size_t)hop * BB * SS + b * SS;

    float u[8];
#pragma unroll
    for (int i = 0; i < 8; i++) {
        const float* p = P + (size_t)(tid + i * 256) * NCHUNK;
        float t = 0.f;
#pragma unroll
        for (int c = 0; c < NCHUNK; c++) t += p[c];
        u[i] = t;
    }
    float m = u[0];
#pragma unroll
    for (int i = 1; i < 8; i++) m = fmaxf(m, u[i]);
    red[tid] = m; __syncthreads();
    for (int o = 128; o > 0; o >>= 1) { if (tid < o) red[tid] = fmaxf(red[tid], red[tid + o]); __syncthreads(); }
    float mx = red[0]; __syncthreads();
    float e[8], sum = 0.f;
#pragma unroll
    for (int i = 0; i < 8; i++) { e[i] = expf(u[i] - mx); sum += e[i]; }
    red[tid] = sum; __syncthreads();
    for (int o = 128; o > 0; o >>= 1) { if (tid < o) red[tid] += red[tid + o]; __syncthreads(); }
    float inv = 1.f / red[0];
#pragma unroll
    for (int i = 0; i < 8; i++) al[tid + i * 256] = e[i] * inv;
}

// ---------------------------------------------------------------
// weighted column sums for BOTH hops in one X pass
// ---------------------------------------------------------------
__global__ void colsum_w2(const float* __restrict__ X) {
    int h  = blockIdx.x * 256 + threadIdx.x;
    int sc = blockIdx.y, b = blockIdx.z;
    const float* base = X + ((size_t)b * SS + (size_t)sc * 128) * HH + h;
    const float* a1 = g_alpha + b * SS + sc * 128;
    const float* a2 = g_alpha + BB * SS + b * SS + sc * 128;
    float acc1 = 0.f, acc2 = 0.f;
#pragma unroll 4
    for (int i = 0; i < 128; i++) {
        float x = base[(size_t)i * HH];
        acc1 = fmaf(__ldg(&a1[i]), x, acc1);
        acc2 = fmaf(__ldg(&a2[i]), x, acc2);
    }
    g_partial [(b * SC + sc) * HH + h] = acc1;
    g_partial2[(b * SC + sc) * HH + h] = acc2;
}

__global__ void finalize_att2(float* __restrict__ out) {
    int idx = blockIdx.x * 256 + threadIdx.x;
    int b = idx >> 10, h = idx & (HH - 1);
    float s1 = 0.f, s2 = 0.f;
#pragma unroll
    for (int c = 0; c < SC; c++) {
        s1 += g_partial [(b * SC + c) * HH + h];
        s2 += g_partial2[(b * SC + c) * HH + h];
    }
    out[(size_t)1 * BB * HH + idx] = s1;
    out[(size_t)2 * BB * HH + idx] = s2;
}

// ---------------------------------------------------------------
extern "C" void kernel_launch(void* const* d_in, const int* in_sizes, int n_in,
                              void* d_out, int out_size) {
    (void)in_sizes; (void)n_in; (void)out_size;
    const float* X   = (const float*)d_in[0];
    const float* q   = (const float*)d_in[1];
    const float* W1  = (const float*)d_in[2];
    const float* Wm1 = (const float*)d_in[3];
    const float* Wh1 = (const float*)d_in[4];
    const float* W2  = (const float*)d_in[5];
    const float* Wm2 = (const float*)d_in[6];
    const float* Wh2 = (const float*)d_in[7];
    float* out = (float*)d_out;

    cudaFuncSetAttribute(gemm_mma, cudaFuncAttributeMaxDynamicSharedMemorySize, SM_TOTAL);

    convW<<<dim3(32, 32, 2), dim3(32, 8)>>>(W1, W2);
    convX_mean<<<dim3(HH / 256, SC, BB), 256>>>(X);
    finalize_mean<<<BB * HH / 256, 256>>>(q, out);
    prep_v<<<dim3(HH / 256, BB / 8, 2), 256>>>(Wm1, Wh1, Wm2, Wh2);

    gemm_mma<<<dim3(NCHUNK, ROWS / 128, 2), 256, SM_TOTAL>>>();

    softmax_u<<<dim3(BB, 2), 256>>>();
    colsum_w2<<<dim3(HH / 256, SC, BB), 256>>>(X);
    finalize_att2<<<BB * HH / 256, 256>>>(out);
}

// round 4
// speedup vs baseline: 7.4334x; 1.1128x over previous
#include <cuda_runtime.h>
#include <cuda_bf16.h>
#include <math.h>
#include <stdint.h>

#define BB 32
#define SS 2048
#define HH 1024
#define SC 16
#define ROWS (BB*SS)          // 65536
#define NCHUNK 8

// ---------------- device scratch (no allocs allowed) ----------------
__device__ __nv_bfloat16 g_Xb[(size_t)ROWS * HH];   // 128 MB bf16 X
__device__ __nv_bfloat16 g_Wt1[HH * HH];            // W1^T bf16 [d][k]
__device__ __nv_bfloat16 g_Wt2[HH * HH];            // W2^T bf16
__device__ float g_partial [BB * SC * HH];
__device__ float g_partial2[BB * SC * HH];
__device__ float g_m0[BB * HH];
__device__ float g_v1[BB * HH];
__device__ float g_v2[BB * HH];
__device__ float g_pU[(size_t)2 * ROWS * NCHUNK];   // per-hop partial U
__device__ float g_alpha[2 * BB * SS];

// ---------------- helpers ----------------
__device__ __forceinline__ uint32_t sm_u32(const void* p) {
    uint32_t a;
    asm("{ .reg .u64 t; cvta.to.shared.u64 t, %1; cvt.u32.u64 %0, t; }" : "=r"(a) : "l"(p));
    return a;
}
__device__ __forceinline__ float ftanh(float x) {
    float y; asm("tanh.approx.f32 %0, %1;" : "=f"(y) : "f"(x)); return y;
}

#define CP16(dst, src) \
    asm volatile("cp.async.cg.shared.global [%0], [%1], 16;\n" \
        :: "r"(dst), "l"(__cvta_generic_to_global(src)))
#define CP_COMMIT()    asm volatile("cp.async.commit_group;\n" ::: "memory")
#define CP_WAIT(n)     asm volatile("cp.async.wait_group %0;\n" :: "n"(n) : "memory")

__device__ __forceinline__ void ldsm4(uint32_t& r0, uint32_t& r1, uint32_t& r2, uint32_t& r3, uint32_t a) {
    asm volatile("ldmatrix.sync.aligned.m8n8.x4.shared.b16 {%0,%1,%2,%3}, [%4];"
        : "=r"(r0), "=r"(r1), "=r"(r2), "=r"(r3) : "r"(a));
}
__device__ __forceinline__ void mma16816(float* d, const uint32_t* a, const uint32_t* b) {
    asm volatile("mma.sync.aligned.m16n8k16.row.col.f32.bf16.bf16.f32 "
        "{%0,%1,%2,%3}, {%4,%5,%6,%7}, {%8,%9}, {%0,%1,%2,%3};"
        : "+f"(d[0]), "+f"(d[1]), "+f"(d[2]), "+f"(d[3])
        : "r"(a[0]), "r"(a[1]), "r"(a[2]), "r"(a[3]), "r"(b[0]), "r"(b[1]));
}

// ---------------- SMEM layout for GEMM (dynamic) ----------------
#define SMA 0
#define SMB 32768
#define SMV 65536           // 128 floats of v
#define SMU 66048           // Upart[4][128] floats
#define SM_TOTAL 68096

// ---------------------------------------------------------------
// convert W -> bf16 transposed: Wt[d][k] = bf16(W[k][d])
// ---------------------------------------------------------------
__global__ void convW(const float* __restrict__ W1, const float* __restrict__ W2) {
    __shared__ float t[32][33];
    const float* W = blockIdx.z ? W2 : W1;
    __nv_bfloat16* Wt = blockIdx.z ? g_Wt2 : g_Wt1;
    int d0 = blockIdx.x * 32, k0 = blockIdx.y * 32;
    int tx = threadIdx.x, ty = threadIdx.y;
    for (int j = ty; j < 32; j += 8)
        t[j][tx] = W[(size_t)(k0 + j) * HH + d0 + tx];
    __syncthreads();
    for (int j = ty; j < 32; j += 8)
        Wt[(size_t)(d0 + j) * HH + k0 + tx] = __float2bfloat16(t[tx][j]);
}

// ---------------------------------------------------------------
// convert X -> bf16 + partial column sums (mean), one X pass
// ---------------------------------------------------------------
__global__ void convX_mean(const float* __restrict__ X) {
    int h  = blockIdx.x * 256 + threadIdx.x;
    int sc = blockIdx.y, b = blockIdx.z;
    size_t base = ((size_t)b * SS + (size_t)sc * 128) * HH + h;
    float acc = 0.f;
#pragma unroll 4
    for (int i = 0; i < 128; i++) {
        float x = X[base + (size_t)i * HH];
        acc += x;
        g_Xb[base + (size_t)i * HH] = __float2bfloat16(x);
    }
    g_partial[(b * SC + sc) * HH + h] = acc;
}

__global__ void finalize_mean(const float* __restrict__ q, float* __restrict__ out) {
    int idx = blockIdx.x * 256 + threadIdx.x;
    int b = idx >> 10, h = idx & (HH - 1);
    float s = 0.f;
#pragma unroll
    for (int c = 0; c < SC; c++) s += g_partial[(b * SC + c) * HH + h];
    float mean = s * (1.f / (float)SS);
    g_m0[idx] = mean * q[idx];
    out[idx]  = mean;                          // u_att0
}

// ---------------------------------------------------------------
// v[b,d] = tanh(scale*(m0@Wm)[b,d]) * Wh[d];  hop2: m1=2*m0 -> scale=2
// grid (HH/256, BB, 2), block 256: one (d, b) pair per thread.
// ---------------------------------------------------------------
__global__ void __launch_bounds__(256) prep_v(
        const float* __restrict__ Wm1, const float* __restrict__ Wh1,
        const float* __restrict__ Wm2, const float* __restrict__ Wh2) {
    __shared__ float sm[HH];
    int d   = blockIdx.x * 256 + threadIdx.x;
    int b   = blockIdx.y;
    int hop = blockIdx.z;
    const float* Wm = hop ? Wm2 : Wm1;
    const float* Wh = hop ? Wh2 : Wh1;
    float scale = hop ? 2.f : 1.f;

    // stage m0 row
    {
        const float4* src = (const float4*)(g_m0 + b * HH);
        float4* dst = (float4*)sm;
        if (threadIdx.x < HH / 4) dst[threadIdx.x] = src[threadIdx.x];
    }
    __syncthreads();

    float a0 = 0.f, a1 = 0.f, a2 = 0.f, a3 = 0.f;
    const float* wp = Wm + d;
#pragma unroll 2
    for (int k = 0; k < HH; k += 8) {
        a0 = fmaf(sm[k + 0], wp[(size_t)(k + 0) * HH], a0);
        a1 = fmaf(sm[k + 1], wp[(size_t)(k + 1) * HH], a1);
        a2 = fmaf(sm[k + 2], wp[(size_t)(k + 2) * HH], a2);
        a3 = fmaf(sm[k + 3], wp[(size_t)(k + 3) * HH], a3);
        a0 = fmaf(sm[k + 4], wp[(size_t)(k + 4) * HH], a0);
        a1 = fmaf(sm[k + 5], wp[(size_t)(k + 5) * HH], a1);
        a2 = fmaf(sm[k + 6], wp[(size_t)(k + 6) * HH], a2);
        a3 = fmaf(sm[k + 7], wp[(size_t)(k + 7) * HH], a3);
    }
    float acc = (a0 + a1) + (a2 + a3);
    float* v = hop ? g_v2 : g_v1;
    v[b * HH + d] = tanhf(scale * acc) * Wh[d];
}

// ---------------------------------------------------------------
// HMMA GEMM + fused tanh/v-dot epilogue.
// grid (NCHUNK*2, ROWS/128): x = nch*2 + hop (hop fastest for X L2 reuse).
// 256 threads = 2 (M) x 4 (N) warps. Warp tile 64x32, mma m16n8k16 bf16.
// ---------------------------------------------------------------
__device__ __forceinline__ void stage_load(uint32_t sb, int st,
                                           const __nv_bfloat16* Xrow,
                                           const __nv_bfloat16* Wrow,
                                           int k0, int tid) {
    uint32_t ab = sb + SMA + st * 16384;
    uint32_t bb = sb + SMB + st * 16384;
#pragma unroll
    for (int i = 0; i < 4; i++) {
        int c = tid + i * 256;            // 1024 16B-chunks
        int r = c >> 3, seg = c & 7;
        uint32_t off = (uint32_t)(r * 128 + seg * 16);
        uint32_t sw  = off ^ ((off >> 3) & 0x70);
        CP16(ab + sw, (const char*)(Xrow + (size_t)r * HH + k0) + seg * 16);
        CP16(bb + sw, (const char*)(Wrow + (size_t)r * HH + k0) + seg * 16);
    }
}

__global__ void __launch_bounds__(256, 2) gemm_mma() {
    extern __shared__ char smem[];
    uint32_t sb = sm_u32(smem);
    int tid = threadIdx.x, lane = tid & 31, wid = tid >> 5;
    int warpM = wid & 1, warpN = wid >> 1;           // 2 x 4
    int hop = blockIdx.x & 1, nch = blockIdx.x >> 1;
    int rowt = blockIdx.y;
    int row0 = rowt * 128, n0 = nch * 128;
    int b = rowt >> 4;

    const __nv_bfloat16* Xrow = g_Xb + (size_t)row0 * HH;
    const __nv_bfloat16* Wrow = (hop ? g_Wt2 : g_Wt1) + (size_t)n0 * HH;
    const float* v = (hop ? g_v2 : g_v1) + b * HH + n0;

    float* vs = (float*)(smem + SMV);
    float* su = (float*)(smem + SMU);
    if (tid < 128) vs[tid] = v[tid];

    float acc[4][4][4];
#pragma unroll
    for (int i = 0; i < 4; i++)
#pragma unroll
        for (int j = 0; j < 4; j++)
#pragma unroll
            for (int t = 0; t < 4; t++) acc[i][j][t] = 0.f;

    int rA = warpM * 64 + (lane & 15);
    uint32_t rxA = (uint32_t)((rA & 7) << 4);
    uint32_t aoff = (uint32_t)(((lane >> 4) & 1) << 4);
    int rB = warpN * 32 + (lane & 7) + ((lane & 16) >> 1);
    uint32_t rxB = (uint32_t)((rB & 7) << 4);
    uint32_t boff = (uint32_t)(((lane >> 3) & 1) << 4);

    stage_load(sb, 0, Xrow, Wrow, 0, tid);  CP_COMMIT();
    stage_load(sb, 1, Xrow, Wrow, 64, tid); CP_COMMIT();

    for (int kk = 0; kk < 16; kk++) {
        int st = kk & 1;
        if (kk < 15) { CP_WAIT(1); } else { CP_WAIT(0); }
        __syncthreads();

        uint32_t abase = sb + SMA + st * 16384;
        uint32_t bbase = sb + SMB + st * 16384;
#pragma unroll
        for (int s = 0; s < 4; s++) {
            uint32_t A[4][4];
#pragma unroll
            for (int i = 0; i < 4; i++) {
                uint32_t addr = abase + (uint32_t)((rA + i * 16) * 128)
                              + (((uint32_t)(s * 32) + aoff) ^ rxA);
                ldsm4(A[i][0], A[i][1], A[i][2], A[i][3], addr);
            }
            uint32_t Bf[4][2];
#pragma unroll
            for (int jj = 0; jj < 2; jj++) {
                uint32_t addr = bbase + (uint32_t)((rB + jj * 16) * 128)
                              + (((uint32_t)(s * 32) + boff) ^ rxB);
                ldsm4(Bf[jj*2][0], Bf[jj*2][1], Bf[jj*2+1][0], Bf[jj*2+1][1], addr);
            }
#pragma unroll
            for (int i = 0; i < 4; i++)
#pragma unroll
                for (int j = 0; j < 4; j++)
                    mma16816(acc[i][j], A[i], Bf[j]);
        }
        __syncthreads();
        if (kk < 14) {
            stage_load(sb, st, Xrow, Wrow, (kk + 2) * 64, tid);
            CP_COMMIT();
        }
    }

    // epilogue: tanh * v, reduce over n
    float vv[4][2];
#pragma unroll
    for (int j = 0; j < 4; j++) {
        int nl = warpN * 32 + j * 8 + (lane & 3) * 2;
        vv[j][0] = vs[nl]; vv[j][1] = vs[nl + 1];
    }
#pragma unroll
    for (int i = 0; i < 4; i++) {
        float r0 = 0.f, r1 = 0.f;
#pragma unroll
        for (int j = 0; j < 4; j++) {
            r0 = fmaf(ftanh(acc[i][j][0]), vv[j][0], r0);
            r0 = fmaf(ftanh(acc[i][j][1]), vv[j][1], r0);
            r1 = fmaf(ftanh(acc[i][j][2]), vv[j][0], r1);
            r1 = fmaf(ftanh(acc[i][j][3]), vv[j][1], r1);
        }
        r0 += __shfl_xor_sync(0xffffffffu, r0, 1);
        r0 += __shfl_xor_sync(0xffffffffu, r0, 2);
        r1 += __shfl_xor_sync(0xffffffffu, r1, 1);
        r1 += __shfl_xor_sync(0xffffffffu, r1, 2);
        if ((lane & 3) == 0) {
            int r = warpM * 64 + i * 16 + (lane >> 2);
            su[warpN * 128 + r]     = r0;
            su[warpN * 128 + r + 8] = r1;
        }
    }
    __syncthreads();
    if (tid < 128) {
        float s = su[tid] + su[128 + tid] + su[256 + tid] + su[384 + tid];
        g_pU[((size_t)hop * ROWS + row0 + tid) * NCHUNK + nch] = s;
    }
}

// ---------------------------------------------------------------
// reduce partial U + softmax over S, both hops. grid (B, 2), block 256.
// ---------------------------------------------------------------
__global__ void softmax_u() {
    int b = blockIdx.x, hop = blockIdx.y;
    int tid = threadIdx.x;
    __shared__ float red[256];
    const float* P = g_pU + ((size_t)hop * ROWS + (size_t)b * SS) * NCHUNK;
    float* al = g_alpha + (size_t)hop * BB * SS + b * SS;

    float u[8];
#pragma unroll
    for (int i = 0; i < 8; i++) {
        const float* p = P + (size_t)(tid + i * 256) * NCHUNK;
        float t = 0.f;
#pragma unroll
        for (int c = 0; c < NCHUNK; c++) t += p[c];
        u[i] = t;
    }
    float m = u[0];
#pragma unroll
    for (int i = 1; i < 8; i++) m = fmaxf(m, u[i]);
    red[tid] = m; __syncthreads();
    for (int o = 128; o > 0; o >>= 1) { if (tid < o) red[tid] = fmaxf(red[tid], red[tid + o]); __syncthreads(); }
    float mx = red[0]; __syncthreads();
    float e[8], sum = 0.f;
#pragma unroll
    for (int i = 0; i < 8; i++) { e[i] = expf(u[i] - mx); sum += e[i]; }
    red[tid] = sum; __syncthreads();
    for (int o = 128; o > 0; o >>= 1) { if (tid < o) red[tid] += red[tid + o]; __syncthreads(); }
    float inv = 1.f / red[0];
#pragma unroll
    for (int i = 0; i < 8; i++) al[tid + i * 256] = e[i] * inv;
}

// ---------------------------------------------------------------
// weighted column sums for BOTH hops in one X pass
// ---------------------------------------------------------------
__global__ void colsum_w2(const float* __restrict__ X) {
    int h  = blockIdx.x * 256 + threadIdx.x;
    int sc = blockIdx.y, b = blockIdx.z;
    const float* base = X + ((size_t)b * SS + (size_t)sc * 128) * HH + h;
    const float* a1 = g_alpha + b * SS + sc * 128;
    const float* a2 = g_alpha + BB * SS + b * SS + sc * 128;
    float acc1 = 0.f, acc2 = 0.f;
#pragma unroll 4
    for (int i = 0; i < 128; i++) {
        float x = base[(size_t)i * HH];
        acc1 = fmaf(__ldg(&a1[i]), x, acc1);
        acc2 = fmaf(__ldg(&a2[i]), x, acc2);
    }
    g_partial [(b * SC + sc) * HH + h] = acc1;
    g_partial2[(b * SC + sc) * HH + h] = acc2;
}

__global__ void finalize_att2(float* __restrict__ out) {
    int idx = blockIdx.x * 256 + threadIdx.x;
    int b = idx >> 10, h = idx & (HH - 1);
    float s1 = 0.f, s2 = 0.f;
#pragma unroll
    for (int c = 0; c < SC; c++) {
        s1 += g_partial [(b * SC + c) * HH + h];
        s2 += g_partial2[(b * SC + c) * HH + h];
    }
    out[(size_t)1 * BB * HH + idx] = s1;
    out[(size_t)2 * BB * HH + idx] = s2;
}

// ---------------------------------------------------------------
extern "C" void kernel_launch(void* const* d_in, const int* in_sizes, int n_in,
                              void* d_out, int out_size) {
    (void)in_sizes; (void)n_in; (void)out_size;
    const float* X   = (const float*)d_in[0];
    const float* q   = (const float*)d_in[1];
    const float* W1  = (const float*)d_in[2];
    const float* Wm1 = (const float*)d_in[3];
    const float* Wh1 = (const float*)d_in[4];
    const float* W2  = (const float*)d_in[5];
    const float* Wm2 = (const float*)d_in[6];
    const float* Wh2 = (const float*)d_in[7];
    float* out = (float*)d_out;

    cudaFuncSetAttribute(gemm_mma, cudaFuncAttributeMaxDynamicSharedMemorySize, SM_TOTAL);

    convW<<<dim3(32, 32, 2), dim3(32, 8)>>>(W1, W2);
    convX_mean<<<dim3(HH / 256, SC, BB), 256>>>(X);
    finalize_mean<<<BB * HH / 256, 256>>>(q, out);
    prep_v<<<dim3(HH / 256, BB, 2), 256>>>(Wm1, Wh1, Wm2, Wh2);

    gemm_mma<<<dim3(NCHUNK * 2, ROWS / 128), 256, SM_TOTAL>>>();

    softmax_u<<<dim3(BB, 2), 256>>>();
    colsum_w2<<<dim3(HH / 256, SC, BB), 256>>>(X);
    finalize_att2<<<BB * HH / 256, 256>>>(out);
}

// round 5
// speedup vs baseline: 7.5329x; 1.0134x over previous
#include <cuda_runtime.h>
#include <cuda_bf16.h>
#include <math.h>
#include <stdint.h>

#define BB 32
#define SS 2048
#define HH 1024
#define SC 16
#define ROWS (BB*SS)          // 65536
#define NCHUNK 8

// ---------------- device scratch (no allocs allowed) ----------------
__device__ __nv_bfloat16 g_Xb[(size_t)ROWS * HH];   // 128 MB bf16 X
__device__ __nv_bfloat16 g_Wt1[HH * HH];            // W1^T bf16 [d][k]
__device__ __nv_bfloat16 g_Wt2[HH * HH];            // W2^T bf16
__device__ float g_partial [BB * SC * HH];
__device__ float g_partial2[BB * SC * HH];
__device__ float g_m0[BB * HH];
__device__ float g_v1[BB * HH];
__device__ float g_v2[BB * HH];
__device__ float g_vpart[2 * 8 * BB * HH];          // split-k partials for v
__device__ float g_pU[(size_t)2 * ROWS * NCHUNK];   // per-hop partial U
__device__ float g_alpha[2 * BB * SS];

// ---------------- helpers ----------------
__device__ __forceinline__ uint32_t sm_u32(const void* p) {
    uint32_t a;
    asm("{ .reg .u64 t; cvta.to.shared.u64 t, %1; cvt.u32.u64 %0, t; }" : "=r"(a) : "l"(p));
    return a;
}
__device__ __forceinline__ float ftanh(float x) {
    float y; asm("tanh.approx.f32 %0, %1;" : "=f"(y) : "f"(x)); return y;
}

#define CP16(dst, src) \
    asm volatile("cp.async.cg.shared.global [%0], [%1], 16;\n" \
        :: "r"(dst), "l"(__cvta_generic_to_global(src)))
#define CP_COMMIT()    asm volatile("cp.async.commit_group;\n" ::: "memory")
#define CP_WAIT(n)     asm volatile("cp.async.wait_group %0;\n" :: "n"(n) : "memory")

__device__ __forceinline__ void ldsm4(uint32_t& r0, uint32_t& r1, uint32_t& r2, uint32_t& r3, uint32_t a) {
    asm volatile("ldmatrix.sync.aligned.m8n8.x4.shared.b16 {%0,%1,%2,%3}, [%4];"
        : "=r"(r0), "=r"(r1), "=r"(r2), "=r"(r3) : "r"(a));
}
__device__ __forceinline__ void mma16816(float* d, const uint32_t* a, const uint32_t* b) {
    asm volatile("mma.sync.aligned.m16n8k16.row.col.f32.bf16.bf16.f32 "
        "{%0,%1,%2,%3}, {%4,%5,%6,%7}, {%8,%9}, {%0,%1,%2,%3};"
        : "+f"(d[0]), "+f"(d[1]), "+f"(d[2]), "+f"(d[3])
        : "r"(a[0]), "r"(a[1]), "r"(a[2]), "r"(a[3]), "r"(b[0]), "r"(b[1]));
}

// ---------------- SMEM layout for GEMM (3-stage) ----------------
#define SMA 0               // 3 x 16384
#define SMB 49152           // 3 x 16384
#define SMV 98304           // 128 floats of v
#define SMU 98816           // Upart[4][128] floats
#define SM_TOTAL 100864

// ---------------------------------------------------------------
// convert W -> bf16 transposed: Wt[d][k] = bf16(W[k][d])
// ---------------------------------------------------------------
__global__ void convW(const float* __restrict__ W1, const float* __restrict__ W2) {
    __shared__ float t[32][33];
    const float* W = blockIdx.z ? W2 : W1;
    __nv_bfloat16* Wt = blockIdx.z ? g_Wt2 : g_Wt1;
    int d0 = blockIdx.x * 32, k0 = blockIdx.y * 32;
    int tx = threadIdx.x, ty = threadIdx.y;
    for (int j = ty; j < 32; j += 8)
        t[j][tx] = W[(size_t)(k0 + j) * HH + d0 + tx];
    __syncthreads();
    for (int j = ty; j < 32; j += 8)
        Wt[(size_t)(d0 + j) * HH + k0 + tx] = __float2bfloat16(t[tx][j]);
}

// ---------------------------------------------------------------
// convert X -> bf16 + partial column sums, vectorized (4 h per thread)
// grid (SC, BB), block 256
// ---------------------------------------------------------------
__global__ void __launch_bounds__(256) convX_mean(const float* __restrict__ X) {
    int sc = blockIdx.x, b = blockIdx.y;
    int h0 = threadIdx.x * 4;
    size_t base = ((size_t)b * SS + (size_t)sc * 128) * HH + h0;
    float a0 = 0.f, a1 = 0.f, a2 = 0.f, a3 = 0.f;
#pragma unroll 4
    for (int i = 0; i < 128; i++) {
        float4 x = *(const float4*)(X + base + (size_t)i * HH);
        a0 += x.x; a1 += x.y; a2 += x.z; a3 += x.w;
        __nv_bfloat162 p0 = __floats2bfloat162_rn(x.x, x.y);
        __nv_bfloat162 p1 = __floats2bfloat162_rn(x.z, x.w);
        uint2 u;
        u.x = *(uint32_t*)&p0;
        u.y = *(uint32_t*)&p1;
        *(uint2*)(g_Xb + base + (size_t)i * HH) = u;
    }
    *(float4*)(g_partial + (b * SC + sc) * HH + h0) = make_float4(a0, a1, a2, a3);
}

__global__ void finalize_mean(const float* __restrict__ q, float* __restrict__ out) {
    int idx = blockIdx.x * 256 + threadIdx.x;
    int b = idx >> 10, h = idx & (HH - 1);
    float s = 0.f;
#pragma unroll
    for (int c = 0; c < SC; c++) s += g_partial[(b * SC + c) * HH + h];
    float mean = s * (1.f / (float)SS);
    g_m0[idx] = mean * q[idx];
    out[idx]  = mean;                          // u_att0
}

// ---------------------------------------------------------------
// v partials: split-K over Wm. grid (8 dtile, 8 ksplit, 2 hop), block 256.
// Each thread: 4 b x 4 d register tile; Wm read exactly once from DRAM.
// ---------------------------------------------------------------
__global__ void __launch_bounds__(256) prep_v_part(
        const float* __restrict__ Wm1, const float* __restrict__ Wm2) {
    __shared__ float sm0[128 * 32];            // [k][b]
    int hop = blockIdx.z, ks = blockIdx.y, dt = blockIdx.x;
    const float* Wm = hop ? Wm2 : Wm1;
    int d0 = dt * 128, k0 = ks * 128;

    for (int i = threadIdx.x; i < 128 * 32; i += 256) {
        int b = i & 31, k = i >> 5;
        sm0[i] = g_m0[b * HH + k0 + k];
    }
    __syncthreads();

    int dl = (threadIdx.x & 31) * 4;
    int bg = (threadIdx.x >> 5) * 4;
    const float* Wp = Wm + (size_t)k0 * HH + d0 + dl;

    float acc[4][4];
#pragma unroll
    for (int j = 0; j < 4; j++)
#pragma unroll
        for (int t = 0; t < 4; t++) acc[j][t] = 0.f;

#pragma unroll 4
    for (int k = 0; k < 128; k++) {
        float4 w = *(const float4*)(Wp + (size_t)k * HH);
        const float* mk = sm0 + k * 32 + bg;
#pragma unroll
        for (int j = 0; j < 4; j++) {
            float m = mk[j];
            acc[j][0] = fmaf(m, w.x, acc[j][0]);
            acc[j][1] = fmaf(m, w.y, acc[j][1]);
            acc[j][2] = fmaf(m, w.z, acc[j][2]);
            acc[j][3] = fmaf(m, w.w, acc[j][3]);
        }
    }
    float* dst = g_vpart + (size_t)(hop * 8 + ks) * BB * HH;
#pragma unroll
    for (int j = 0; j < 4; j++)
        *(float4*)(dst + (bg + j) * HH + d0 + dl) =
            make_float4(acc[j][0], acc[j][1], acc[j][2], acc[j][3]);
}

__global__ void finalize_v(const float* __restrict__ Wh1, const float* __restrict__ Wh2) {
    int idx = blockIdx.x * 256 + threadIdx.x;    // < 2*BB*HH
    int hop = idx >> 15;
    int r = idx & (BB * HH - 1);
    int d = r & (HH - 1);
    float s = 0.f;
#pragma unroll
    for (int ks = 0; ks < 8; ks++)
        s += g_vpart[(size_t)(hop * 8 + ks) * BB * HH + r];
    float scale = hop ? 2.f : 1.f;
    const float* Wh = hop ? Wh2 : Wh1;
    (hop ? g_v2 : g_v1)[r] = tanhf(scale * s) * Wh[d];
}

// ---------------------------------------------------------------
// HMMA GEMM + fused tanh/v-dot epilogue. 3-stage cp.async pipeline.
// grid (NCHUNK*2, ROWS/128): x = nch*2 + hop (hop fastest for X L2 reuse).
// ---------------------------------------------------------------
__device__ __forceinline__ void stage_load(uint32_t sb, int st,
                                           const __nv_bfloat16* Xrow,
                                           const __nv_bfloat16* Wrow,
                                           int k0, int tid) {
    uint32_t ab = sb + SMA + st * 16384;
    uint32_t bb = sb + SMB + st * 16384;
#pragma unroll
    for (int i = 0; i < 4; i++) {
        int c = tid + i * 256;            // 1024 16B-chunks
        int r = c >> 3, seg = c & 7;
        uint32_t off = (uint32_t)(r * 128 + seg * 16);
        uint32_t sw  = off ^ ((off >> 3) & 0x70);
        CP16(ab + sw, (const char*)(Xrow + (size_t)r * HH + k0) + seg * 16);
        CP16(bb + sw, (const char*)(Wrow + (size_t)r * HH + k0) + seg * 16);
    }
}

__global__ void __launch_bounds__(256, 2) gemm_mma() {
    extern __shared__ char smem[];
    uint32_t sb = sm_u32(smem);
    int tid = threadIdx.x, lane = tid & 31, wid = tid >> 5;
    int warpM = wid & 1, warpN = wid >> 1;           // 2 x 4
    int hop = blockIdx.x & 1, nch = blockIdx.x >> 1;
    int rowt = blockIdx.y;
    int row0 = rowt * 128, n0 = nch * 128;
    int b = rowt >> 4;

    const __nv_bfloat16* Xrow = g_Xb + (size_t)row0 * HH;
    const __nv_bfloat16* Wrow = (hop ? g_Wt2 : g_Wt1) + (size_t)n0 * HH;
    const float* v = (hop ? g_v2 : g_v1) + b * HH + n0;

    float* vs = (float*)(smem + SMV);
    float* su = (float*)(smem + SMU);
    if (tid < 128) vs[tid] = v[tid];

    float acc[4][4][4];
#pragma unroll
    for (int i = 0; i < 4; i++)
#pragma unroll
        for (int j = 0; j < 4; j++)
#pragma unroll
            for (int t = 0; t < 4; t++) acc[i][j][t] = 0.f;

    int rA = warpM * 64 + (lane & 15);
    uint32_t rxA = (uint32_t)((rA & 7) << 4);
    uint32_t aoff = (uint32_t)(((lane >> 4) & 1) << 4);
    int rB = warpN * 32 + (lane & 7) + ((lane & 16) >> 1);
    uint32_t rxB = (uint32_t)((rB & 7) << 4);
    uint32_t boff = (uint32_t)(((lane >> 3) & 1) << 4);

    stage_load(sb, 0, Xrow, Wrow, 0,   tid); CP_COMMIT();
    stage_load(sb, 1, Xrow, Wrow, 64,  tid); CP_COMMIT();
    stage_load(sb, 2, Xrow, Wrow, 128, tid); CP_COMMIT();

    int st = 0;
    for (int kk = 0; kk < 16; kk++) {
        if (kk < 14) { CP_WAIT(2); }
        else if (kk == 14) { CP_WAIT(1); }
        else { CP_WAIT(0); }
        __syncthreads();

        uint32_t abase = sb + SMA + st * 16384;
        uint32_t bbase = sb + SMB + st * 16384;
#pragma unroll
        for (int s = 0; s < 4; s++) {
            uint32_t A[4][4];
#pragma unroll
            for (int i = 0; i < 4; i++) {
                uint32_t addr = abase + (uint32_t)((rA + i * 16) * 128)
                              + (((uint32_t)(s * 32) + aoff) ^ rxA);
                ldsm4(A[i][0], A[i][1], A[i][2], A[i][3], addr);
            }
            uint32_t Bf[4][2];
#pragma unroll
            for (int jj = 0; jj < 2; jj++) {
                uint32_t addr = bbase + (uint32_t)((rB + jj * 16) * 128)
                              + (((uint32_t)(s * 32) + boff) ^ rxB);
                ldsm4(Bf[jj*2][0], Bf[jj*2][1], Bf[jj*2+1][0], Bf[jj*2+1][1], addr);
            }
#pragma unroll
            for (int i = 0; i < 4; i++)
#pragma unroll
                for (int j = 0; j < 4; j++)
                    mma16816(acc[i][j], A[i], Bf[j]);
        }
        __syncthreads();
        if (kk < 13) {
            stage_load(sb, st, Xrow, Wrow, (kk + 3) * 64, tid);
            CP_COMMIT();
        }
        st = (st == 2) ? 0 : st + 1;
    }

    // epilogue: tanh * v, reduce over n
    float vv[4][2];
#pragma unroll
    for (int j = 0; j < 4; j++) {
        int nl = warpN * 32 + j * 8 + (lane & 3) * 2;
        vv[j][0] = vs[nl]; vv[j][1] = vs[nl + 1];
    }
#pragma unroll
    for (int i = 0; i < 4; i++) {
        float r0 = 0.f, r1 = 0.f;
#pragma unroll
        for (int j = 0; j < 4; j++) {
            r0 = fmaf(ftanh(acc[i][j][0]), vv[j][0], r0);
            r0 = fmaf(ftanh(acc[i][j][1]), vv[j][1], r0);
            r1 = fmaf(ftanh(acc[i][j][2]), vv[j][0], r1);
            r1 = fmaf(ftanh(acc[i][j][3]), vv[j][1], r1);
        }
        r0 += __shfl_xor_sync(0xffffffffu, r0, 1);
        r0 += __shfl_xor_sync(0xffffffffu, r0, 2);
        r1 += __shfl_xor_sync(0xffffffffu, r1, 1);
        r1 += __shfl_xor_sync(0xffffffffu, r1, 2);
        if ((lane & 3) == 0) {
            int r = warpM * 64 + i * 16 + (lane >> 2);
            su[warpN * 128 + r]     = r0;
            su[warpN * 128 + r + 8] = r1;
        }
    }
    __syncthreads();
    if (tid < 128) {
        float s = su[tid] + su[128 + tid] + su[256 + tid] + su[384 + tid];
        g_pU[((size_t)hop * ROWS + row0 + tid) * NCHUNK + nch] = s;
    }
}

// ---------------------------------------------------------------
// reduce partial U + softmax over S, both hops. grid (B, 2), block 256.
// ---------------------------------------------------------------
__global__ void softmax_u() {
    int b = blockIdx.x, hop = blockIdx.y;
    int tid = threadIdx.x;
    __shared__ float red[256];
    const float* P = g_pU + ((size_t)hop * ROWS + (size_t)b * SS) * NCHUNK;
    float* al = g_alpha + (size_t)hop * BB * SS + b * SS;

    float u[8];
#pragma unroll
    for (int i = 0; i < 8; i++) {
        const float* p = P + (size_t)(tid + i * 256) * NCHUNK;
        float t = 0.f;
#pragma unroll
        for (int c = 0; c < NCHUNK; c++) t += p[c];
        u[i] = t;
    }
    float m = u[0];
#pragma unroll
    for (int i = 1; i < 8; i++) m = fmaxf(m, u[i]);
    red[tid] = m; __syncthreads();
    for (int o = 128; o > 0; o >>= 1) { if (tid < o) red[tid] = fmaxf(red[tid], red[tid + o]); __syncthreads(); }
    float mx = red[0]; __syncthreads();
    float e[8], sum = 0.f;
#pragma unroll
    for (int i = 0; i < 8; i++) { e[i] = expf(u[i] - mx); sum += e[i]; }
    red[tid] = sum; __syncthreads();
    for (int o = 128; o > 0; o >>= 1) { if (tid < o) red[tid] += red[tid + o]; __syncthreads(); }
    float inv = 1.f / red[0];
#pragma unroll
    for (int i = 0; i < 8; i++) al[tid + i * 256] = e[i] * inv;
}

// ---------------------------------------------------------------
// weighted column sums for BOTH hops in one X pass
// ---------------------------------------------------------------
__global__ void colsum_w2(const float* __restrict__ X) {
    int h  = blockIdx.x * 256 + threadIdx.x;
    int sc = blockIdx.y, b = blockIdx.z;
    const float* base = X + ((size_t)b * SS + (size_t)sc * 128) * HH + h;
    const float* a1 = g_alpha + b * SS + sc * 128;
    const float* a2 = g_alpha + BB * SS + b * SS + sc * 128;
    float acc1 = 0.f, acc2 = 0.f;
#pragma unroll 4
    for (int i = 0; i < 128; i++) {
        float x = base[(size_t)i * HH];
        acc1 = fmaf(__ldg(&a1[i]), x, acc1);
        acc2 = fmaf(__ldg(&a2[i]), x, acc2);
    }
    g_partial [(b * SC + sc) * HH + h] = acc1;
    g_partial2[(b * SC + sc) * HH + h] = acc2;
}

__global__ void finalize_att2(float* __restrict__ out) {
    int idx = blockIdx.x * 256 + threadIdx.x;
    int b = idx >> 10, h = idx & (HH - 1);
    float s1 = 0.f, s2 = 0.f;
#pragma unroll
    for (int c = 0; c < SC; c++) {
        s1 += g_partial [(b * SC + c) * HH + h];
        s2 += g_partial2[(b * SC + c) * HH + h];
    }
    out[(size_t)1 * BB * HH + idx] = s1;
    out[(size_t)2 * BB * HH + idx] = s2;
}

// ---------------------------------------------------------------
extern "C" void kernel_launch(void* const* d_in, const int* in_sizes, int n_in,
                              void* d_out, int out_size) {
    (void)in_sizes; (void)n_in; (void)out_size;
    const float* X   = (const float*)d_in[0];
    const float* q   = (const float*)d_in[1];
    const float* W1  = (const float*)d_in[2];
    const float* Wm1 = (const float*)d_in[3];
    const float* Wh1 = (const float*)d_in[4];
    const float* W2  = (const float*)d_in[5];
    const float* Wm2 = (const float*)d_in[6];
    const float* Wh2 = (const float*)d_in[7];
    float* out = (float*)d_out;

    cudaFuncSetAttribute(gemm_mma, cudaFuncAttributeMaxDynamicSharedMemorySize, SM_TOTAL);

    convW<<<dim3(32, 32, 2), dim3(32, 8)>>>(W1, W2);
    convX_mean<<<dim3(SC, BB), 256>>>(X);
    finalize_mean<<<BB * HH / 256, 256>>>(q, out);
    prep_v_part<<<dim3(8, 8, 2), 256>>>(Wm1, Wm2);
    finalize_v<<<2 * BB * HH / 256, 256>>>(Wh1, Wh2);

    gemm_mma<<<dim3(NCHUNK * 2, ROWS / 128), 256, SM_TOTAL>>>();

    softmax_u<<<dim3(BB, 2), 256>>>();
    colsum_w2<<<dim3(HH / 256, SC, BB), 256>>>(X);
    finalize_att2<<<BB * HH / 256, 256>>>(out);
}

// round 6
// speedup vs baseline: 8.0611x; 1.0701x over previous
#include <cuda_runtime.h>
#include <cuda_bf16.h>
#include <math.h>
#include <stdint.h>

#define BB 32
#define SS 2048
#define HH 1024
#define SC 16
#define ROWS (BB*SS)          // 65536
#define NCHUNK 8
#define VKS 32                // v split-K factor

// ---------------- device scratch (no allocs allowed) ----------------
__device__ __nv_bfloat16 g_Xb[(size_t)ROWS * HH];   // 128 MB bf16 X
__device__ __nv_bfloat16 g_Wt1[HH * HH];            // W1^T bf16 [d][k]
__device__ __nv_bfloat16 g_Wt2[HH * HH];            // W2^T bf16
__device__ float g_partial [BB * SC * HH];
__device__ float g_partial2[BB * SC * HH];
__device__ float g_m0[BB * HH];
__device__ float g_v1[BB * HH];
__device__ float g_v2[BB * HH];
__device__ float g_vpart[2 * VKS * BB * HH];        // split-k partials for v
__device__ float g_pU[(size_t)2 * ROWS * NCHUNK];   // per-hop partial U
__device__ float g_alpha[2 * BB * SS];

// ---------------- helpers ----------------
__device__ __forceinline__ uint32_t sm_u32(const void* p) {
    uint32_t a;
    asm("{ .reg .u64 t; cvta.to.shared.u64 t, %1; cvt.u32.u64 %0, t; }" : "=r"(a) : "l"(p));
    return a;
}
__device__ __forceinline__ float ftanh(float x) {
    float y; asm("tanh.approx.f32 %0, %1;" : "=f"(y) : "f"(x)); return y;
}

#define CP16(dst, src) \
    asm volatile("cp.async.cg.shared.global [%0], [%1], 16;\n" \
        :: "r"(dst), "l"(__cvta_generic_to_global(src)))
#define CP_COMMIT()    asm volatile("cp.async.commit_group;\n" ::: "memory")
#define CP_WAIT(n)     asm volatile("cp.async.wait_group %0;\n" :: "n"(n) : "memory")

__device__ __forceinline__ void ldsm4(uint32_t& r0, uint32_t& r1, uint32_t& r2, uint32_t& r3, uint32_t a) {
    asm volatile("ldmatrix.sync.aligned.m8n8.x4.shared.b16 {%0,%1,%2,%3}, [%4];"
        : "=r"(r0), "=r"(r1), "=r"(r2), "=r"(r3) : "r"(a));
}
__device__ __forceinline__ void mma16816(float* d, const uint32_t* a, const uint32_t* b) {
    asm volatile("mma.sync.aligned.m16n8k16.row.col.f32.bf16.bf16.f32 "
        "{%0,%1,%2,%3}, {%4,%5,%6,%7}, {%8,%9}, {%0,%1,%2,%3};"
        : "+f"(d[0]), "+f"(d[1]), "+f"(d[2]), "+f"(d[3])
        : "r"(a[0]), "r"(a[1]), "r"(a[2]), "r"(a[3]), "r"(b[0]), "r"(b[1]));
}

// ---------------- SMEM layout for GEMM (3-stage) ----------------
#define SMA 0               // 3 x 16384
#define SMB 49152           // 3 x 16384
#define SMV 98304           // 128 floats of v
#define SMU 98816           // Upart[4][128] floats
#define SM_TOTAL 100864

// ---------------------------------------------------------------
// convert W -> bf16 transposed: Wt[d][k] = bf16(W[k][d])
// ---------------------------------------------------------------
__global__ void convW(const float* __restrict__ W1, const float* __restrict__ W2) {
    __shared__ float t[32][33];
    const float* W = blockIdx.z ? W2 : W1;
    __nv_bfloat16* Wt = blockIdx.z ? g_Wt2 : g_Wt1;
    int d0 = blockIdx.x * 32, k0 = blockIdx.y * 32;
    int tx = threadIdx.x, ty = threadIdx.y;
    for (int j = ty; j < 32; j += 8)
        t[j][tx] = W[(size_t)(k0 + j) * HH + d0 + tx];
    __syncthreads();
    for (int j = ty; j < 32; j += 8)
        Wt[(size_t)(d0 + j) * HH + k0 + tx] = __float2bfloat16(t[tx][j]);
}

// ---------------------------------------------------------------
// convert X -> bf16 + partial column sums, vectorized (4 h per thread)
// grid (SC, BB), block 256
// ---------------------------------------------------------------
__global__ void __launch_bounds__(256) convX_mean(const float* __restrict__ X) {
    int sc = blockIdx.x, b = blockIdx.y;
    int h0 = threadIdx.x * 4;
    size_t base = ((size_t)b * SS + (size_t)sc * 128) * HH + h0;
    float a0 = 0.f, a1 = 0.f, a2 = 0.f, a3 = 0.f;
#pragma unroll 4
    for (int i = 0; i < 128; i++) {
        float4 x = *(const float4*)(X + base + (size_t)i * HH);
        a0 += x.x; a1 += x.y; a2 += x.z; a3 += x.w;
        __nv_bfloat162 p0 = __floats2bfloat162_rn(x.x, x.y);
        __nv_bfloat162 p1 = __floats2bfloat162_rn(x.z, x.w);
        uint2 u;
        u.x = *(uint32_t*)&p0;
        u.y = *(uint32_t*)&p1;
        *(uint2*)(g_Xb + base + (size_t)i * HH) = u;
    }
    *(float4*)(g_partial + (b * SC + sc) * HH + h0) = make_float4(a0, a1, a2, a3);
}

__global__ void finalize_mean(const float* __restrict__ q, float* __restrict__ out) {
    int idx = blockIdx.x * 256 + threadIdx.x;
    int b = idx >> 10, h = idx & (HH - 1);
    float s = 0.f;
#pragma unroll
    for (int c = 0; c < SC; c++) s += g_partial[(b * SC + c) * HH + h];
    float mean = s * (1.f / (float)SS);
    g_m0[idx] = mean * q[idx];
    out[idx]  = mean;                          // u_att0
}

// ---------------------------------------------------------------
// v partials: split-K(32) over Wm. grid (8 dtile, 32 ksplit, 2 hop), 256 thr.
// 512 blocks / 131K threads: enough MLP in flight to saturate DRAM.
// ---------------------------------------------------------------
__global__ void __launch_bounds__(256) prep_v_part(
        const float* __restrict__ Wm1, const float* __restrict__ Wm2) {
    __shared__ float sm0[32 * 32];             // [k][b]
    int hop = blockIdx.z, ks = blockIdx.y, dt = blockIdx.x;
    const float* Wm = hop ? Wm2 : Wm1;
    int d0 = dt * 128, k0 = ks * 32;

    for (int i = threadIdx.x; i < 32 * 32; i += 256) {
        int b = i & 31, k = i >> 5;
        sm0[i] = g_m0[b * HH + k0 + k];
    }
    __syncthreads();

    int dl = (threadIdx.x & 31) * 4;
    int bg = (threadIdx.x >> 5) * 4;
    const float* Wp = Wm + (size_t)k0 * HH + d0 + dl;

    float acc[4][4];
#pragma unroll
    for (int j = 0; j < 4; j++)
#pragma unroll
        for (int t = 0; t < 4; t++) acc[j][t] = 0.f;

#pragma unroll 8
    for (int k = 0; k < 32; k++) {
        float4 w = *(const float4*)(Wp + (size_t)k * HH);
        const float* mk = sm0 + k * 32 + bg;
#pragma unroll
        for (int j = 0; j < 4; j++) {
            float m = mk[j];
            acc[j][0] = fmaf(m, w.x, acc[j][0]);
            acc[j][1] = fmaf(m, w.y, acc[j][1]);
            acc[j][2] = fmaf(m, w.z, acc[j][2]);
            acc[j][3] = fmaf(m, w.w, acc[j][3]);
        }
    }
    float* dst = g_vpart + (size_t)(hop * VKS + ks) * BB * HH;
#pragma unroll
    for (int j = 0; j < 4; j++)
        *(float4*)(dst + (bg + j) * HH + d0 + dl) =
            make_float4(acc[j][0], acc[j][1], acc[j][2], acc[j][3]);
}

__global__ void finalize_v(const float* __restrict__ Wh1, const float* __restrict__ Wh2) {
    int idx = blockIdx.x * 256 + threadIdx.x;    // < 2*BB*HH
    int hop = idx >> 15;
    int r = idx & (BB * HH - 1);
    int d = r & (HH - 1);
    float s = 0.f;
#pragma unroll 8
    for (int ks = 0; ks < VKS; ks++)
        s += g_vpart[(size_t)(hop * VKS + ks) * BB * HH + r];
    float scale = hop ? 2.f : 1.f;
    const float* Wh = hop ? Wh2 : Wh1;
    (hop ? g_v2 : g_v1)[r] = tanhf(scale * s) * Wh[d];
}

// ---------------------------------------------------------------
// HMMA GEMM + fused tanh/v-dot epilogue. 3-stage cp.async pipeline.
// grid (NCHUNK*2, ROWS/128): x = nch*2 + hop (hop fastest for X L2 reuse).
// ---------------------------------------------------------------
__device__ __forceinline__ void stage_load(uint32_t sb, int st,
                                           const __nv_bfloat16* Xrow,
                                           const __nv_bfloat16* Wrow,
                                           int k0, int tid) {
    uint32_t ab = sb + SMA + st * 16384;
    uint32_t bb = sb + SMB + st * 16384;
#pragma unroll
    for (int i = 0; i < 4; i++) {
        int c = tid + i * 256;            // 1024 16B-chunks
        int r = c >> 3, seg = c & 7;
        uint32_t off = (uint32_t)(r * 128 + seg * 16);
        uint32_t sw  = off ^ ((off >> 3) & 0x70);
        CP16(ab + sw, (const char*)(Xrow + (size_t)r * HH + k0) + seg * 16);
        CP16(bb + sw, (const char*)(Wrow + (size_t)r * HH + k0) + seg * 16);
    }
}

__global__ void __launch_bounds__(256, 2) gemm_mma() {
    extern __shared__ char smem[];
    uint32_t sb = sm_u32(smem);
    int tid = threadIdx.x, lane = tid & 31, wid = tid >> 5;
    int warpM = wid & 1, warpN = wid >> 1;           // 2 x 4
    int hop = blockIdx.x & 1, nch = blockIdx.x >> 1;
    int rowt = blockIdx.y;
    int row0 = rowt * 128, n0 = nch * 128;
    int b = rowt >> 4;

    const __nv_bfloat16* Xrow = g_Xb + (size_t)row0 * HH;
    const __nv_bfloat16* Wrow = (hop ? g_Wt2 : g_Wt1) + (size_t)n0 * HH;
    const float* v = (hop ? g_v2 : g_v1) + b * HH + n0;

    float* vs = (float*)(smem + SMV);
    float* su = (float*)(smem + SMU);
    if (tid < 128) vs[tid] = v[tid];

    float acc[4][4][4];
#pragma unroll
    for (int i = 0; i < 4; i++)
#pragma unroll
        for (int j = 0; j < 4; j++)
#pragma unroll
            for (int t = 0; t < 4; t++) acc[i][j][t] = 0.f;

    int rA = warpM * 64 + (lane & 15);
    uint32_t rxA = (uint32_t)((rA & 7) << 4);
    uint32_t aoff = (uint32_t)(((lane >> 4) & 1) << 4);
    int rB = warpN * 32 + (lane & 7) + ((lane & 16) >> 1);
    uint32_t rxB = (uint32_t)((rB & 7) << 4);
    uint32_t boff = (uint32_t)(((lane >> 3) & 1) << 4);

    stage_load(sb, 0, Xrow, Wrow, 0,   tid); CP_COMMIT();
    stage_load(sb, 1, Xrow, Wrow, 64,  tid); CP_COMMIT();
    stage_load(sb, 2, Xrow, Wrow, 128, tid); CP_COMMIT();

    int st = 0;
    for (int kk = 0; kk < 16; kk++) {
        if (kk < 14) { CP_WAIT(2); }
        else if (kk == 14) { CP_WAIT(1); }
        else { CP_WAIT(0); }
        __syncthreads();

        uint32_t abase = sb + SMA + st * 16384;
        uint32_t bbase = sb + SMB + st * 16384;
#pragma unroll
        for (int s = 0; s < 4; s++) {
            uint32_t A[4][4];
#pragma unroll
            for (int i = 0; i < 4; i++) {
                uint32_t addr = abase + (uint32_t)((rA + i * 16) * 128)
                              + (((uint32_t)(s * 32) + aoff) ^ rxA);
                ldsm4(A[i][0], A[i][1], A[i][2], A[i][3], addr);
            }
            uint32_t Bf[4][2];
#pragma unroll
            for (int jj = 0; jj < 2; jj++) {
                uint32_t addr = bbase + (uint32_t)((rB + jj * 16) * 128)
                              + (((uint32_t)(s * 32) + boff) ^ rxB);
                ldsm4(Bf[jj*2][0], Bf[jj*2][1], Bf[jj*2+1][0], Bf[jj*2+1][1], addr);
            }
#pragma unroll
            for (int i = 0; i < 4; i++)
#pragma unroll
                for (int j = 0; j < 4; j++)
                    mma16816(acc[i][j], A[i], Bf[j]);
        }
        __syncthreads();
        if (kk < 13) {
            stage_load(sb, st, Xrow, Wrow, (kk + 3) * 64, tid);
            CP_COMMIT();
        }
        st = (st == 2) ? 0 : st + 1;
    }

    // epilogue: tanh * v, reduce over n
    float vv[4][2];
#pragma unroll
    for (int j = 0; j < 4; j++) {
        int nl = warpN * 32 + j * 8 + (lane & 3) * 2;
        vv[j][0] = vs[nl]; vv[j][1] = vs[nl + 1];
    }
#pragma unroll
    for (int i = 0; i < 4; i++) {
        float r0 = 0.f, r1 = 0.f;
#pragma unroll
        for (int j = 0; j < 4; j++) {
            r0 = fmaf(ftanh(acc[i][j][0]), vv[j][0], r0);
            r0 = fmaf(ftanh(acc[i][j][1]), vv[j][1], r0);
            r1 = fmaf(ftanh(acc[i][j][2]), vv[j][0], r1);
            r1 = fmaf(ftanh(acc[i][j][3]), vv[j][1], r1);
        }
        r0 += __shfl_xor_sync(0xffffffffu, r0, 1);
        r0 += __shfl_xor_sync(0xffffffffu, r0, 2);
        r1 += __shfl_xor_sync(0xffffffffu, r1, 1);
        r1 += __shfl_xor_sync(0xffffffffu, r1, 2);
        if ((lane & 3) == 0) {
            int r = warpM * 64 + i * 16 + (lane >> 2);
            su[warpN * 128 + r]     = r0;
            su[warpN * 128 + r + 8] = r1;
        }
    }
    __syncthreads();
    if (tid < 128) {
        float s = su[tid] + su[128 + tid] + su[256 + tid] + su[384 + tid];
        g_pU[((size_t)hop * ROWS + row0 + tid) * NCHUNK + nch] = s;
    }
}

// ---------------------------------------------------------------
// reduce partial U + softmax over S, both hops. grid (B, 2), block 256.
// ---------------------------------------------------------------
__global__ void softmax_u() {
    int b = blockIdx.x, hop = blockIdx.y;
    int tid = threadIdx.x;
    __shared__ float red[256];
    const float* P = g_pU + ((size_t)hop * ROWS + (size_t)b * SS) * NCHUNK;
    float* al = g_alpha + (size_t)hop * BB * SS + b * SS;

    float u[8];
#pragma unroll
    for (int i = 0; i < 8; i++) {
        const float* p = P + (size_t)(tid + i * 256) * NCHUNK;
        float t = 0.f;
#pragma unroll
        for (int c = 0; c < NCHUNK; c++) t += p[c];
        u[i] = t;
    }
    float m = u[0];
#pragma unroll
    for (int i = 1; i < 8; i++) m = fmaxf(m, u[i]);
    red[tid] = m; __syncthreads();
    for (int o = 128; o > 0; o >>= 1) { if (tid < o) red[tid] = fmaxf(red[tid], red[tid + o]); __syncthreads(); }
    float mx = red[0]; __syncthreads();
    float e[8], sum = 0.f;
#pragma unroll
    for (int i = 0; i < 8; i++) { e[i] = expf(u[i] - mx); sum += e[i]; }
    red[tid] = sum; __syncthreads();
    for (int o = 128; o > 0; o >>= 1) { if (tid < o) red[tid] += red[tid + o]; __syncthreads(); }
    float inv = 1.f / red[0];
#pragma unroll
    for (int i = 0; i < 8; i++) al[tid + i * 256] = e[i] * inv;
}

// ---------------------------------------------------------------
// weighted column sums for BOTH hops in one X pass
// ---------------------------------------------------------------
__global__ void colsum_w2(const float* __restrict__ X) {
    int h  = blockIdx.x * 256 + threadIdx.x;
    int sc = blockIdx.y, b = blockIdx.z;
    const float* base = X + ((size_t)b * SS + (size_t)sc * 128) * HH + h;
    const float* a1 = g_alpha + b * SS + sc * 128;
    const float* a2 = g_alpha + BB * SS + b * SS + sc * 128;
    float acc1 = 0.f, acc2 = 0.f;
#pragma unroll 4
    for (int i = 0; i < 128; i++) {
        float x = base[(size_t)i * HH];
        acc1 = fmaf(__ldg(&a1[i]), x, acc1);
        acc2 = fmaf(__ldg(&a2[i]), x, acc2);
    }
    g_partial [(b * SC + sc) * HH + h] = acc1;
    g_partial2[(b * SC + sc) * HH + h] = acc2;
}

__global__ void finalize_att2(float* __restrict__ out) {
    int idx = blockIdx.x * 256 + threadIdx.x;
    int b = idx >> 10, h = idx & (HH - 1);
    float s1 = 0.f, s2 = 0.f;
#pragma unroll
    for (int c = 0; c < SC; c++) {
        s1 += g_partial [(b * SC + c) * HH + h];
        s2 += g_partial2[(b * SC + c) * HH + h];
    }
    out[(size_t)1 * BB * HH + idx] = s1;
    out[(size_t)2 * BB * HH + idx] = s2;
}

// ---------------------------------------------------------------
extern "C" void kernel_launch(void* const* d_in, const int* in_sizes, int n_in,
                              void* d_out, int out_size) {
    (void)in_sizes; (void)n_in; (void)out_size;
    const float* X   = (const float*)d_in[0];
    const float* q   = (const float*)d_in[1];
    const float* W1  = (const float*)d_in[2];
    const float* Wm1 = (const float*)d_in[3];
    const float* Wh1 = (const float*)d_in[4];
    const float* W2  = (const float*)d_in[5];
    const float* Wm2 = (const float*)d_in[6];
    const float* Wh2 = (const float*)d_in[7];
    float* out = (float*)d_out;

    cudaFuncSetAttribute(gemm_mma, cudaFuncAttributeMaxDynamicSharedMemorySize, SM_TOTAL);

    convW<<<dim3(32, 32, 2), dim3(32, 8)>>>(W1, W2);
    convX_mean<<<dim3(SC, BB), 256>>>(X);
    finalize_mean<<<BB * HH / 256, 256>>>(q, out);
    prep_v_part<<<dim3(8, VKS, 2), 256>>>(Wm1, Wm2);
    finalize_v<<<2 * BB * HH / 256, 256>>>(Wh1, Wh2);

    gemm_mma<<<dim3(NCHUNK * 2, ROWS / 128), 256, SM_TOTAL>>>();

    softmax_u<<<dim3(BB, 2), 256>>>();
    colsum_w2<<<dim3(HH / 256, SC, BB), 256>>>(X);
    finalize_att2<<<BB * HH / 256, 256>>>(out);
}